// round 10
// baseline (speedup 1.0000x reference)
#include <cuda_runtime.h>
#include <math.h>

// Problem constants (B,T,D,U) = (256, 1024, 128, 256)
#define RNN_B 256
#define RNN_T 1024
#define RNN_D 128
#define RNN_U 256

// Scan kernel K-split: per K-half (128 rows), 96 rows of Wh live in registers,
// 32 rows live in shared memory.
#define KREG 96
#define KSM  32

// ---------------------------------------------------------------------------
// Packed fp32x2 helpers (Blackwell FFMA2 path — only reachable via PTX)
// ---------------------------------------------------------------------------
__device__ __forceinline__ unsigned long long ffma2(unsigned long long a,
                                                    unsigned long long b,
                                                    unsigned long long c) {
    unsigned long long d;
    asm("fma.rn.f32x2 %0, %1, %2, %3;" : "=l"(d) : "l"(a), "l"(b), "l"(c));
    return d;
}
__device__ __forceinline__ unsigned long long fadd2(unsigned long long a,
                                                    unsigned long long b) {
    unsigned long long d;
    asm("add.rn.f32x2 %0, %1, %2;" : "=l"(d) : "l"(a), "l"(b));
    return d;
}
__device__ __forceinline__ unsigned long long pack2(float x, float y) {
    unsigned long long r;
    asm("mov.b64 %0, {%1, %2};" : "=l"(r) : "f"(x), "f"(y));
    return r;
}
__device__ __forceinline__ void unpack2(unsigned long long v, float& x, float& y) {
    asm("mov.b64 {%0, %1}, %2;" : "=f"(x), "=f"(y) : "l"(v));
}

// ---------------------------------------------------------------------------
// Kernel 1: x_proj = x @ Wx + bias, written into d_out (same shape as output).
// Block = 128 threads; thread p owns output columns (2p, 2p+1) for a 32-row
// tile. x tile is staged in smem pre-duplicated as {v,v} so the inner loop is
// pure LDS.64(broadcast) + FFMA2. Wx (128 KB) stays L2-resident.
// ---------------------------------------------------------------------------
__global__ __launch_bounds__(128) void xproj_kernel(
        const float* __restrict__ x, const float* __restrict__ W,
        const float* __restrict__ bias, float* __restrict__ out) {
    __shared__ unsigned long long sx[32 * 128];  // 32 KB, duplicated x tile

    const int p = threadIdx.x;                   // u-pair index, 0..127
    const size_t r0 = (size_t)blockIdx.x * 32;   // first (b*t) row of tile

    // Stage x tile (coalesced), duplicating each value into both f32x2 lanes.
#pragma unroll
    for (int i = 0; i < 32; i++) {
        float v = x[(r0 + i) * RNN_D + p];
        sx[i * 128 + p] = pack2(v, v);
    }
    __syncthreads();

    unsigned long long b2 =
        *reinterpret_cast<const unsigned long long*>(bias + 2 * p);
    unsigned long long acc[32];
#pragma unroll
    for (int r = 0; r < 32; r++) acc[r] = b2;

    // Wx = W[U:], row-major (D rows of U floats)
    const float* wp = W + (size_t)RNN_U * RNN_U + 2 * p;
#pragma unroll 2
    for (int d = 0; d < RNN_D; d++) {
        unsigned long long wv =
            *reinterpret_cast<const unsigned long long*>(wp + (size_t)d * RNN_U);
#pragma unroll
        for (int r = 0; r < 32; r++)
            acc[r] = ffma2(wv, sx[r * 128 + d], acc[r]);
    }

#pragma unroll
    for (int r = 0; r < 32; r++)
        *reinterpret_cast<unsigned long long*>(out + (r0 + r) * RNN_U + 2 * p) =
            acc[r];
}

// ---------------------------------------------------------------------------
// Kernel 2: persistent batch-parallel scan. 128 CTAs, 2 batches each, 256 thr.
//   s = tid>>7 : K-half (k in [s*128, s*128+128))
//   p = tid&127: output pair (2p, 2p+1)
// Wh rows [s*128, s*128+96) live in 96 u64 registers/thread (192 KB/SM total);
// rows [s*128+96, s*128+128) live in smem (64 KB). h is kept in smem
// pre-duplicated as {h,h} so every MAC is LDS.64(broadcast)+FFMA2.
// Per step: partial sums from s=1 half go through smem, s=0 half adds xp
// (prefetched from d_out), applies tanh, writes h back to d_out in place.
// ---------------------------------------------------------------------------
__global__ __launch_bounds__(256, 1) void rnn_scan_kernel(
        const float* __restrict__ W, const float* __restrict__ h0,
        float* __restrict__ out) {
    extern __shared__ unsigned long long smem[];
    unsigned long long* sWh  = smem;                 // [64][128] u-pairs (64 KB)
    unsigned long long* sh   = smem + 64 * 128;      // [2][256] duplicated h (4 KB)
    unsigned long long* sred = sh + 2 * 256;         // [2][128] partials (2 KB)

    const int tid = threadIdx.x;
    const int s = tid >> 7;
    const int p = tid & 127;
    const int b0 = blockIdx.x * 2;

    // --- load register-resident Wh slice: k = s*128 + j, j in [0,96) ---
    unsigned long long wreg[KREG];
    {
        const float* wbase = W + (size_t)(s * 128) * RNN_U + 2 * p;
#pragma unroll
        for (int j = 0; j < KREG; j++)
            wreg[j] = *reinterpret_cast<const unsigned long long*>(
                wbase + (size_t)j * RNN_U);
    }
    // --- stage smem-resident Wh rows: k = s2*128 + 96 + j, j in [0,32) ---
    for (int idx = tid; idx < 64 * 128; idx += 256) {
        int row = idx >> 7;   // 0..63
        int col = idx & 127;
        int k = (row >> 5) * 128 + KREG + (row & 31);
        sWh[idx] = *reinterpret_cast<const unsigned long long*>(
            W + (size_t)k * RNN_U + 2 * col);
    }
    // --- initial h from h0 (duplicated lanes) ---
    for (int idx = tid; idx < 2 * RNN_U; idx += 256) {
        int g = idx >> 8;
        int u = idx & 255;
        float h = h0[(size_t)(b0 + g) * RNN_U + u];
        sh[idx] = pack2(h, h);
    }
    __syncthreads();

    float* r0p = out + (size_t)b0 * RNN_T * RNN_U + 2 * p;        // batch b0
    float* r1p = out + (size_t)(b0 + 1) * RNN_T * RNN_U + 2 * p;  // batch b0+1

    for (int t = 0; t < RNN_T; t++) {
        // Prefetch x_proj for this step early (latency hidden by FMA loops).
        unsigned long long xpa = 0, xpb = 0;
        if (s == 0) {
            xpa = *reinterpret_cast<const unsigned long long*>(r0p);
            xpb = *reinterpret_cast<const unsigned long long*>(r1p);
        }

        unsigned long long a0 = 0, a0b = 0, a1 = 0, a1b = 0;
        const unsigned long long* sh0 = sh + s * 128;        // batch 0, this K-half
        const unsigned long long* sh1 = sh + 256 + s * 128;  // batch 1

        // Register-weight MACs (96 k-rows x 2 batches), 4 accumulator chains.
#pragma unroll
        for (int j = 0; j < KREG; j += 2) {
            a0  = ffma2(wreg[j],     sh0[j],     a0);
            a1  = ffma2(wreg[j],     sh1[j],     a1);
            a0b = ffma2(wreg[j + 1], sh0[j + 1], a0b);
            a1b = ffma2(wreg[j + 1], sh1[j + 1], a1b);
        }
        // Smem-weight MACs (32 k-rows x 2 batches).
        const unsigned long long* sw = sWh + (s * KSM) * 128 + p;
#pragma unroll
        for (int j = 0; j < KSM; j += 2) {
            unsigned long long w0 = sw[j * 128];
            unsigned long long w1 = sw[(j + 1) * 128];
            a0  = ffma2(w0, sh0[KREG + j],     a0);
            a1  = ffma2(w0, sh1[KREG + j],     a1);
            a0b = ffma2(w1, sh0[KREG + j + 1], a0b);
            a1b = ffma2(w1, sh1[KREG + j + 1], a1b);
        }
        a0 = fadd2(a0, a0b);
        a1 = fadd2(a1, a1b);

        if (s == 1) {           // publish upper-half partial sums
            sred[p]       = a0;
            sred[128 + p] = a1;
        }
        __syncthreads();        // partials visible; all sh reads complete

        if (s == 0) {
            unsigned long long z0 = fadd2(fadd2(a0, sred[p]), xpa);
            unsigned long long z1 = fadd2(fadd2(a1, sred[128 + p]), xpb);
            float z0x, z0y, z1x, z1y;
            unpack2(z0, z0x, z0y);
            unpack2(z1, z1x, z1y);
            float h00 = tanhf(z0x), h01 = tanhf(z0y);
            float h10 = tanhf(z1x), h11 = tanhf(z1y);
            // Output (overwrites x_proj slot for this t, in place).
            *reinterpret_cast<unsigned long long*>(r0p) = pack2(h00, h01);
            *reinterpret_cast<unsigned long long*>(r1p) = pack2(h10, h11);
            // Refresh duplicated h for next step.
            sh[2 * p]           = pack2(h00, h00);
            sh[2 * p + 1]       = pack2(h01, h01);
            sh[256 + 2 * p]     = pack2(h10, h10);
            sh[256 + 2 * p + 1] = pack2(h11, h11);
        }
        __syncthreads();        // new h visible before next step's reads

        r0p += RNN_U;
        r1p += RNN_U;
    }
}

// ---------------------------------------------------------------------------
// Launch: x_proj fills d_out, then the scan rewrites it in place.
// Inputs (metadata order): x, h0, W, bias. Output dtype float32.
// ---------------------------------------------------------------------------
extern "C" void kernel_launch(void* const* d_in, const int* in_sizes, int n_in,
                              void* d_out, int out_size) {
    const float* x    = (const float*)d_in[0];
    const float* h0   = (const float*)d_in[1];
    const float* W    = (const float*)d_in[2];
    const float* bias = (const float*)d_in[3];
    float* out = (float*)d_out;

    const int smem_bytes = (64 * 128 + 2 * 256 + 2 * 128) * 8;  // 71680 B
    cudaFuncSetAttribute(rnn_scan_kernel,
                         cudaFuncAttributeMaxDynamicSharedMemorySize, smem_bytes);

    xproj_kernel<<<(RNN_B * RNN_T) / 32, 128>>>(x, W, bias, out);
    rnn_scan_kernel<<<RNN_B / 2, 256, smem_bytes>>>(W, h0, out);
}

// round 11
// speedup vs baseline: 1.2043x; 1.2043x over previous
#include <cuda_runtime.h>
#include <math.h>

// Problem constants (B,T,D,U) = (256, 1024, 128, 256)
#define RNN_B 256
#define RNN_T 1024
#define RNN_D 128
#define RNN_U 256

// Scan K-quarter split: per quarter (64 rows), 48 rows of Wh in registers,
// 16 rows in shared memory.
#define KREG 48
#define KSM  16

typedef unsigned long long u64;

// ---------------------------------------------------------------------------
// Packed fp32x2 helpers (Blackwell FFMA2 path — only reachable via PTX)
// ---------------------------------------------------------------------------
__device__ __forceinline__ u64 ffma2(u64 a, u64 b, u64 c) {
    u64 d;
    asm("fma.rn.f32x2 %0, %1, %2, %3;" : "=l"(d) : "l"(a), "l"(b), "l"(c));
    return d;
}
__device__ __forceinline__ u64 fadd2(u64 a, u64 b) {
    u64 d;
    asm("add.rn.f32x2 %0, %1, %2;" : "=l"(d) : "l"(a), "l"(b));
    return d;
}
__device__ __forceinline__ u64 pack2(float x, float y) {
    u64 r;
    asm("mov.b64 %0, {%1, %2};" : "=l"(r) : "f"(x), "f"(y));
    return r;
}
__device__ __forceinline__ void unpack2(u64 v, float& x, float& y) {
    asm("mov.b64 {%0, %1}, %2;" : "=f"(x), "=f"(y) : "l"(v));
}

// Fast accurate-enough tanh: 1 - 2/(e^{2x}+1). Saturates correctly for |x|
// large (exp->inf or 0). Error ~1e-6, far inside the 1e-3 gate.
__device__ __forceinline__ float tanh_fast(float x) {
    float e = __expf(2.0f * x);
    return 1.0f - 2.0f / (e + 1.0f);
}

// ---------------------------------------------------------------------------
// Kernel 1: x_proj = x @ Wx + bias -> d_out (scan overwrites in place).
// 256 threads/CTA, tile = 64 (b*t) rows x 256 u.
//   g = tid>>6: row subgroup (16 rows), p = tid&63: u-quad (u = 4p..4p+3).
// x staged in smem duplicated {v,v}; inner loop fetches TWO dup-pairs per
// broadcast LDS.128 (1 crossbar phase). Wx via L2-resident LDG.128.
// ---------------------------------------------------------------------------
__global__ __launch_bounds__(256) void xproj_kernel(
        const float* __restrict__ x, const float* __restrict__ W,
        const float* __restrict__ bias, float* __restrict__ out) {
    extern __shared__ u64 sx[];  // [64 rows][128 d] dup u64 = 64 KB

    const int tid = threadIdx.x;
    const int g = tid >> 6;                      // row subgroup 0..3
    const int p = tid & 63;                      // u-quad index
    const size_t r0 = (size_t)blockIdx.x * 64;   // first (b*t) row of tile

    // Stage x tile, duplicated into both f32x2 lanes.
    for (int idx = tid; idx < 64 * RNN_D; idx += 256) {
        int r = idx >> 7;
        int d = idx & 127;
        float v = x[(r0 + r) * RNN_D + d];
        sx[idx] = pack2(v, v);
    }
    __syncthreads();

    ulonglong2 b2 = *reinterpret_cast<const ulonglong2*>(bias + 4 * p);
    u64 acc0[16], acc1[16];
#pragma unroll
    for (int r = 0; r < 16; r++) { acc0[r] = b2.x; acc1[r] = b2.y; }

    // Wx = W[U:], row-major (D rows of U floats). u64 row stride = 128.
    const u64* wp = reinterpret_cast<const u64*>(
        W + (size_t)RNN_U * RNN_U + 4 * p);
    const u64* sxg = sx + (g * 16) * RNN_D;      // this subgroup's 16 rows

#pragma unroll 2
    for (int d = 0; d < RNN_D; d += 2) {
        ulonglong2 w0 = *reinterpret_cast<const ulonglong2*>(wp + (size_t)d * 128);
        ulonglong2 w1 = *reinterpret_cast<const ulonglong2*>(wp + (size_t)(d + 1) * 128);
#pragma unroll
        for (int r = 0; r < 16; r++) {
            // {x[r][d]dup, x[r][d+1]dup} in one broadcast LDS.128
            ulonglong2 xv = *reinterpret_cast<const ulonglong2*>(sxg + r * RNN_D + d);
            acc0[r] = ffma2(w0.x, xv.x, acc0[r]);
            acc1[r] = ffma2(w0.y, xv.x, acc1[r]);
            acc0[r] = ffma2(w1.x, xv.y, acc0[r]);
            acc1[r] = ffma2(w1.y, xv.y, acc1[r]);
        }
    }

#pragma unroll
    for (int r = 0; r < 16; r++)
        *reinterpret_cast<ulonglong2*>(
            out + (r0 + g * 16 + r) * RNN_U + 4 * p) =
            make_ulonglong2(acc0[r], acc1[r]);
}

// ---------------------------------------------------------------------------
// Kernel 2: persistent batch-parallel scan. 128 CTAs, 2 batches each, 256 thr.
//   s = tid>>6 : K-quarter (k in [64s, 64s+64))
//   p = tid&63 : u-quad, outputs u = 4p..4p+3 (pairs 2p, 2p+1)
// Wh rows [64s, 64s+48) in registers (96 u64/thread); rows [64s+48, 64s+64)
// in smem (64 KB), read via LDS.128. h kept duplicated {h,h}; each broadcast
// LDS.128 yields two dup-pairs in one crossbar phase and feeds 4 FFMA2s.
// Per step: all quarters publish both batches' partials; s=0 finalizes
// batch 0, s=1 finalizes batch 1 (tanh + writeback + h refresh).
// ---------------------------------------------------------------------------
__global__ __launch_bounds__(256, 1) void rnn_scan_kernel(
        const float* __restrict__ W, const float* __restrict__ h0,
        float* __restrict__ out) {
    extern __shared__ u64 smem[];
    u64* sW   = smem;                 // [4][KSM][64][2] = 8192 u64 (64 KB)
    u64* sh   = smem + 8192;          // [2][256] duplicated h (4 KB)
    u64* sred = sh + 512;             // [2][4][64][2] partials (8 KB)

    const int tid = threadIdx.x;
    const int s = tid >> 6;           // K-quarter
    const int p = tid & 63;           // u-quad
    const int b0 = blockIdx.x * 2;

    // --- register-resident Wh: k = 64s + j, j in [0,KREG); 2 u64/row ---
    u64 wr0[KREG], wr1[KREG];
    {
        const u64* wb = reinterpret_cast<const u64*>(
            W + (size_t)(64 * s) * RNN_U + 4 * p);
#pragma unroll
        for (int j = 0; j < KREG; j++) {
            wr0[j] = wb[(size_t)j * 128];
            wr1[j] = wb[(size_t)j * 128 + 1];
        }
    }
    // --- smem-resident Wh: k = 64s + KREG + j, j in [0,KSM) ---
#pragma unroll
    for (int j = 0; j < KSM; j++) {
        int k = 64 * s + KREG + j;
        const u64* wb = reinterpret_cast<const u64*>(
            W + (size_t)k * RNN_U + 4 * p);
        int idx = ((s * KSM + j) * 64 + p) * 2;
        sW[idx]     = wb[0];
        sW[idx + 1] = wb[1];
    }
    // --- initial h from h0 (duplicated lanes) ---
    for (int idx = tid; idx < 2 * RNN_U; idx += 256) {
        int b = idx >> 8;
        int u = idx & 255;
        float h = h0[(size_t)(b0 + b) * RNN_U + u];
        sh[idx] = pack2(h, h);
    }
    __syncthreads();

    float* outb = out + (size_t)(b0 + (s & 1)) * RNN_T * RNN_U + 4 * p;
    const u64* sh0 = sh + 64 * s;          // batch 0 h slice for this quarter
    const u64* sh1 = sh + 256 + 64 * s;    // batch 1
    const u64* swq = sW + (s * KSM) * 128 + 2 * p;
    u64* shb = sh + (s & 1) * 256 + 4 * p; // finalize target (s<2 only)

    for (int t = 0; t < RNN_T; t++) {
        // Prefetch this step's x_proj (latency hidden under the MAC loops).
        ulonglong2 xp = make_ulonglong2(0, 0);
        if (s < 2)
            xp = *reinterpret_cast<const ulonglong2*>(outb + (size_t)t * RNN_U);

        u64 a00 = 0, a01 = 0, a10 = 0, a11 = 0;  // [pair][batch]

        // Register-weight MACs: 48 rows, 2 batches, 2 pairs.
#pragma unroll
        for (int j = 0; j < KREG; j += 2) {
            ulonglong2 hb0 = *reinterpret_cast<const ulonglong2*>(sh0 + j);
            ulonglong2 hb1 = *reinterpret_cast<const ulonglong2*>(sh1 + j);
            a00 = ffma2(wr0[j],     hb0.x, a00);
            a01 = ffma2(wr1[j],     hb0.x, a01);
            a10 = ffma2(wr0[j],     hb1.x, a10);
            a11 = ffma2(wr1[j],     hb1.x, a11);
            a00 = ffma2(wr0[j + 1], hb0.y, a00);
            a01 = ffma2(wr1[j + 1], hb0.y, a01);
            a10 = ffma2(wr0[j + 1], hb1.y, a10);
            a11 = ffma2(wr1[j + 1], hb1.y, a11);
        }
        // Smem-weight MACs: 16 rows.
#pragma unroll
        for (int j = 0; j < KSM; j += 2) {
            ulonglong2 w0  = *reinterpret_cast<const ulonglong2*>(swq + (size_t)j * 128);
            ulonglong2 w1  = *reinterpret_cast<const ulonglong2*>(swq + (size_t)(j + 1) * 128);
            ulonglong2 hb0 = *reinterpret_cast<const ulonglong2*>(sh0 + KREG + j);
            ulonglong2 hb1 = *reinterpret_cast<const ulonglong2*>(sh1 + KREG + j);
            a00 = ffma2(w0.x, hb0.x, a00);
            a01 = ffma2(w0.y, hb0.x, a01);
            a10 = ffma2(w0.x, hb1.x, a10);
            a11 = ffma2(w0.y, hb1.x, a11);
            a00 = ffma2(w1.x, hb0.y, a00);
            a01 = ffma2(w1.y, hb0.y, a01);
            a10 = ffma2(w1.x, hb1.y, a10);
            a11 = ffma2(w1.y, hb1.y, a11);
        }

        // Publish partials for both batches.
        *reinterpret_cast<ulonglong2*>(&sred[((0 * 4 + s) * 64 + p) * 2]) =
            make_ulonglong2(a00, a01);
        *reinterpret_cast<ulonglong2*>(&sred[((1 * 4 + s) * 64 + p) * 2]) =
            make_ulonglong2(a10, a11);
        __syncthreads();   // partials visible; all sh reads of this step done

        if (s < 2) {       // s=0 finalizes batch 0, s=1 finalizes batch 1
            const u64* rb = sred + s * 512;  // 4*64*2 u64 per batch
            ulonglong2 q0 = *reinterpret_cast<const ulonglong2*>(&rb[(0 * 64 + p) * 2]);
            ulonglong2 q1 = *reinterpret_cast<const ulonglong2*>(&rb[(1 * 64 + p) * 2]);
            ulonglong2 q2 = *reinterpret_cast<const ulonglong2*>(&rb[(2 * 64 + p) * 2]);
            ulonglong2 q3 = *reinterpret_cast<const ulonglong2*>(&rb[(3 * 64 + p) * 2]);
            u64 z0 = fadd2(fadd2(q0.x, q1.x), fadd2(q2.x, q3.x));
            u64 z1 = fadd2(fadd2(q0.y, q1.y), fadd2(q2.y, q3.y));
            z0 = fadd2(z0, xp.x);
            z1 = fadd2(z1, xp.y);
            float f0, f1, f2, f3;
            unpack2(z0, f0, f1);
            unpack2(z1, f2, f3);
            f0 = tanh_fast(f0);
            f1 = tanh_fast(f1);
            f2 = tanh_fast(f2);
            f3 = tanh_fast(f3);
            // Output (overwrites x_proj slot for this t, in place).
            *reinterpret_cast<ulonglong2*>(outb + (size_t)t * RNN_U) =
                make_ulonglong2(pack2(f0, f1), pack2(f2, f3));
            // Refresh duplicated h for next step.
            *reinterpret_cast<ulonglong2*>(shb) =
                make_ulonglong2(pack2(f0, f0), pack2(f1, f1));
            *reinterpret_cast<ulonglong2*>(shb + 2) =
                make_ulonglong2(pack2(f2, f2), pack2(f3, f3));
        }
        __syncthreads();   // new h visible before next step's reads
    }
}

// ---------------------------------------------------------------------------
// Launch: x_proj fills d_out, then the scan rewrites it in place.
// Inputs (metadata order): x, h0, W, bias. Output dtype float32.
// ---------------------------------------------------------------------------
extern "C" void kernel_launch(void* const* d_in, const int* in_sizes, int n_in,
                              void* d_out, int out_size) {
    const float* x    = (const float*)d_in[0];
    const float* h0   = (const float*)d_in[1];
    const float* W    = (const float*)d_in[2];
    const float* bias = (const float*)d_in[3];
    float* out = (float*)d_out;

    const int xproj_smem = 64 * RNN_D * 8;                     // 65536 B
    const int scan_smem  = (8192 + 512 + 1024) * 8;            // 77824 B
    cudaFuncSetAttribute(xproj_kernel,
                         cudaFuncAttributeMaxDynamicSharedMemorySize, xproj_smem);
    cudaFuncSetAttribute(rnn_scan_kernel,
                         cudaFuncAttributeMaxDynamicSharedMemorySize, scan_smem);

    xproj_kernel<<<(RNN_B * RNN_T) / 64, 256, xproj_smem>>>(x, W, bias, out);
    rnn_scan_kernel<<<RNN_B / 2, 256, scan_smem>>>(W, h0, out);
}

// round 12
// speedup vs baseline: 1.2051x; 1.0007x over previous
#include <cuda_runtime.h>
#include <math.h>

// Problem constants (B,T,D,U) = (256, 1024, 128, 256)
#define RNN_B 256
#define RNN_T 1024
#define RNN_D 128
#define RNN_U 256

// Scan K-quarter split: per quarter (64 rows), 48 rows of Wh in registers,
// 16 rows in shared memory.
#define KREG 48
#define KSM  16

typedef unsigned long long u64;

// ---------------------------------------------------------------------------
// Packed fp32x2 helpers (Blackwell FFMA2 path — only reachable via PTX)
// ---------------------------------------------------------------------------
__device__ __forceinline__ u64 ffma2(u64 a, u64 b, u64 c) {
    u64 d;
    asm("fma.rn.f32x2 %0, %1, %2, %3;" : "=l"(d) : "l"(a), "l"(b), "l"(c));
    return d;
}
__device__ __forceinline__ u64 fadd2(u64 a, u64 b) {
    u64 d;
    asm("add.rn.f32x2 %0, %1, %2;" : "=l"(d) : "l"(a), "l"(b));
    return d;
}
__device__ __forceinline__ u64 pack2(float x, float y) {
    u64 r;
    asm("mov.b64 %0, {%1, %2};" : "=l"(r) : "f"(x), "f"(y));
    return r;
}
__device__ __forceinline__ void unpack2(u64 v, float& x, float& y) {
    asm("mov.b64 {%0, %1}, %2;" : "=f"(x), "=f"(y) : "l"(v));
}

// Fast accurate-enough tanh: 1 - 2/(e^{2x}+1). Saturates correctly for |x|
// large (exp->inf or 0). Error ~1e-6, far inside the 1e-3 gate.
__device__ __forceinline__ float tanh_fast(float x) {
    float e = __expf(2.0f * x);
    return 1.0f - 2.0f / (e + 1.0f);
}

// ---------------------------------------------------------------------------
// Kernel 1: x_proj = x @ Wx + bias -> d_out (scan overwrites in place).
// 256 threads/CTA, tile = 64 (b*t) rows x 256 u.
//   g = tid>>6: row subgroup (16 rows), p = tid&63: u-quad (u = 4p..4p+3).
// x staged in smem duplicated {v,v}; inner loop fetches TWO dup-pairs per
// broadcast LDS.128 (1 crossbar phase). Wx via L2-resident LDG.128.
// ---------------------------------------------------------------------------
__global__ __launch_bounds__(256) void xproj_kernel(
        const float* __restrict__ x, const float* __restrict__ W,
        const float* __restrict__ bias, float* __restrict__ out) {
    extern __shared__ u64 sx[];  // [64 rows][128 d] dup u64 = 64 KB

    const int tid = threadIdx.x;
    const int g = tid >> 6;                      // row subgroup 0..3
    const int p = tid & 63;                      // u-quad index
    const size_t r0 = (size_t)blockIdx.x * 64;   // first (b*t) row of tile

    // Stage x tile, duplicated into both f32x2 lanes.
    for (int idx = tid; idx < 64 * RNN_D; idx += 256) {
        int r = idx >> 7;
        int d = idx & 127;
        float v = x[(r0 + r) * RNN_D + d];
        sx[idx] = pack2(v, v);
    }
    __syncthreads();

    ulonglong2 b2 = *reinterpret_cast<const ulonglong2*>(bias + 4 * p);
    u64 acc0[16], acc1[16];
#pragma unroll
    for (int r = 0; r < 16; r++) { acc0[r] = b2.x; acc1[r] = b2.y; }

    // Wx = W[U:], row-major (D rows of U floats). u64 row stride = 128.
    const u64* wp = reinterpret_cast<const u64*>(
        W + (size_t)RNN_U * RNN_U + 4 * p);
    const u64* sxg = sx + (g * 16) * RNN_D;      // this subgroup's 16 rows

#pragma unroll 2
    for (int d = 0; d < RNN_D; d += 2) {
        ulonglong2 w0 = *reinterpret_cast<const ulonglong2*>(wp + (size_t)d * 128);
        ulonglong2 w1 = *reinterpret_cast<const ulonglong2*>(wp + (size_t)(d + 1) * 128);
#pragma unroll
        for (int r = 0; r < 16; r++) {
            // {x[r][d]dup, x[r][d+1]dup} in one broadcast LDS.128
            ulonglong2 xv = *reinterpret_cast<const ulonglong2*>(sxg + r * RNN_D + d);
            acc0[r] = ffma2(w0.x, xv.x, acc0[r]);
            acc1[r] = ffma2(w0.y, xv.x, acc1[r]);
            acc0[r] = ffma2(w1.x, xv.y, acc0[r]);
            acc1[r] = ffma2(w1.y, xv.y, acc1[r]);
        }
    }

#pragma unroll
    for (int r = 0; r < 16; r++)
        *reinterpret_cast<ulonglong2*>(
            out + (r0 + g * 16 + r) * RNN_U + 4 * p) =
            make_ulonglong2(acc0[r], acc1[r]);
}

// ---------------------------------------------------------------------------
// Kernel 2: persistent batch-parallel scan. 128 CTAs, 2 batches each, 256 thr.
//   s = tid>>6 : K-quarter (k in [64s, 64s+64))
//   p = tid&63 : u-quad, outputs u = 4p..4p+3 (pairs 2p, 2p+1)
// Wh rows [64s, 64s+48) in registers (96 u64/thread); rows [64s+48, 64s+64)
// in smem (64 KB), read via LDS.128. h kept duplicated {h,h}; each broadcast
// LDS.128 yields two dup-pairs in one crossbar phase and feeds 4 FFMA2s.
// Per step: all quarters publish both batches' partials; s=0 finalizes
// batch 0, s=1 finalizes batch 1 (tanh + writeback + h refresh).
// ---------------------------------------------------------------------------
__global__ __launch_bounds__(256, 1) void rnn_scan_kernel(
        const float* __restrict__ W, const float* __restrict__ h0,
        float* __restrict__ out) {
    extern __shared__ u64 smem[];
    u64* sW   = smem;                 // [4][KSM][64][2] = 8192 u64 (64 KB)
    u64* sh   = smem + 8192;          // [2][256] duplicated h (4 KB)
    u64* sred = sh + 512;             // [2][4][64][2] partials (8 KB)

    const int tid = threadIdx.x;
    const int s = tid >> 6;           // K-quarter
    const int p = tid & 63;           // u-quad
    const int b0 = blockIdx.x * 2;

    // --- register-resident Wh: k = 64s + j, j in [0,KREG); 2 u64/row ---
    u64 wr0[KREG], wr1[KREG];
    {
        const u64* wb = reinterpret_cast<const u64*>(
            W + (size_t)(64 * s) * RNN_U + 4 * p);
#pragma unroll
        for (int j = 0; j < KREG; j++) {
            wr0[j] = wb[(size_t)j * 128];
            wr1[j] = wb[(size_t)j * 128 + 1];
        }
    }
    // --- smem-resident Wh: k = 64s + KREG + j, j in [0,KSM) ---
#pragma unroll
    for (int j = 0; j < KSM; j++) {
        int k = 64 * s + KREG + j;
        const u64* wb = reinterpret_cast<const u64*>(
            W + (size_t)k * RNN_U + 4 * p);
        int idx = ((s * KSM + j) * 64 + p) * 2;
        sW[idx]     = wb[0];
        sW[idx + 1] = wb[1];
    }
    // --- initial h from h0 (duplicated lanes) ---
    for (int idx = tid; idx < 2 * RNN_U; idx += 256) {
        int b = idx >> 8;
        int u = idx & 255;
        float h = h0[(size_t)(b0 + b) * RNN_U + u];
        sh[idx] = pack2(h, h);
    }
    __syncthreads();

    float* outb = out + (size_t)(b0 + (s & 1)) * RNN_T * RNN_U + 4 * p;
    const u64* sh0 = sh + 64 * s;          // batch 0 h slice for this quarter
    const u64* sh1 = sh + 256 + 64 * s;    // batch 1
    const u64* swq = sW + (s * KSM) * 128 + 2 * p;
    u64* shb = sh + (s & 1) * 256 + 4 * p; // finalize target (s<2 only)

    for (int t = 0; t < RNN_T; t++) {
        // Prefetch this step's x_proj (latency hidden under the MAC loops).
        ulonglong2 xp = make_ulonglong2(0, 0);
        if (s < 2)
            xp = *reinterpret_cast<const ulonglong2*>(outb + (size_t)t * RNN_U);

        u64 a00 = 0, a01 = 0, a10 = 0, a11 = 0;  // [pair][batch]

        // Register-weight MACs: 48 rows, 2 batches, 2 pairs.
#pragma unroll
        for (int j = 0; j < KREG; j += 2) {
            ulonglong2 hb0 = *reinterpret_cast<const ulonglong2*>(sh0 + j);
            ulonglong2 hb1 = *reinterpret_cast<const ulonglong2*>(sh1 + j);
            a00 = ffma2(wr0[j],     hb0.x, a00);
            a01 = ffma2(wr1[j],     hb0.x, a01);
            a10 = ffma2(wr0[j],     hb1.x, a10);
            a11 = ffma2(wr1[j],     hb1.x, a11);
            a00 = ffma2(wr0[j + 1], hb0.y, a00);
            a01 = ffma2(wr1[j + 1], hb0.y, a01);
            a10 = ffma2(wr0[j + 1], hb1.y, a10);
            a11 = ffma2(wr1[j + 1], hb1.y, a11);
        }
        // Smem-weight MACs: 16 rows.
#pragma unroll
        for (int j = 0; j < KSM; j += 2) {
            ulonglong2 w0  = *reinterpret_cast<const ulonglong2*>(swq + (size_t)j * 128);
            ulonglong2 w1  = *reinterpret_cast<const ulonglong2*>(swq + (size_t)(j + 1) * 128);
            ulonglong2 hb0 = *reinterpret_cast<const ulonglong2*>(sh0 + KREG + j);
            ulonglong2 hb1 = *reinterpret_cast<const ulonglong2*>(sh1 + KREG + j);
            a00 = ffma2(w0.x, hb0.x, a00);
            a01 = ffma2(w0.y, hb0.x, a01);
            a10 = ffma2(w0.x, hb1.x, a10);
            a11 = ffma2(w0.y, hb1.x, a11);
            a00 = ffma2(w1.x, hb0.y, a00);
            a01 = ffma2(w1.y, hb0.y, a01);
            a10 = ffma2(w1.x, hb1.y, a10);
            a11 = ffma2(w1.y, hb1.y, a11);
        }

        // Publish partials for both batches.
        *reinterpret_cast<ulonglong2*>(&sred[((0 * 4 + s) * 64 + p) * 2]) =
            make_ulonglong2(a00, a01);
        *reinterpret_cast<ulonglong2*>(&sred[((1 * 4 + s) * 64 + p) * 2]) =
            make_ulonglong2(a10, a11);
        __syncthreads();   // partials visible; all sh reads of this step done

        if (s < 2) {       // s=0 finalizes batch 0, s=1 finalizes batch 1
            const u64* rb = sred + s * 512;  // 4*64*2 u64 per batch
            ulonglong2 q0 = *reinterpret_cast<const ulonglong2*>(&rb[(0 * 64 + p) * 2]);
            ulonglong2 q1 = *reinterpret_cast<const ulonglong2*>(&rb[(1 * 64 + p) * 2]);
            ulonglong2 q2 = *reinterpret_cast<const ulonglong2*>(&rb[(2 * 64 + p) * 2]);
            ulonglong2 q3 = *reinterpret_cast<const ulonglong2*>(&rb[(3 * 64 + p) * 2]);
            u64 z0 = fadd2(fadd2(q0.x, q1.x), fadd2(q2.x, q3.x));
            u64 z1 = fadd2(fadd2(q0.y, q1.y), fadd2(q2.y, q3.y));
            z0 = fadd2(z0, xp.x);
            z1 = fadd2(z1, xp.y);
            float f0, f1, f2, f3;
            unpack2(z0, f0, f1);
            unpack2(z1, f2, f3);
            f0 = tanh_fast(f0);
            f1 = tanh_fast(f1);
            f2 = tanh_fast(f2);
            f3 = tanh_fast(f3);
            // Output (overwrites x_proj slot for this t, in place).
            *reinterpret_cast<ulonglong2*>(outb + (size_t)t * RNN_U) =
                make_ulonglong2(pack2(f0, f1), pack2(f2, f3));
            // Refresh duplicated h for next step.
            *reinterpret_cast<ulonglong2*>(shb) =
                make_ulonglong2(pack2(f0, f0), pack2(f1, f1));
            *reinterpret_cast<ulonglong2*>(shb + 2) =
                make_ulonglong2(pack2(f2, f2), pack2(f3, f3));
        }
        __syncthreads();   // new h visible before next step's reads
    }
}

// ---------------------------------------------------------------------------
// Launch: x_proj fills d_out, then the scan rewrites it in place.
// Inputs (metadata order): x, h0, W, bias. Output dtype float32.
// ---------------------------------------------------------------------------
extern "C" void kernel_launch(void* const* d_in, const int* in_sizes, int n_in,
                              void* d_out, int out_size) {
    const float* x    = (const float*)d_in[0];
    const float* h0   = (const float*)d_in[1];
    const float* W    = (const float*)d_in[2];
    const float* bias = (const float*)d_in[3];
    float* out = (float*)d_out;

    const int xproj_smem = 64 * RNN_D * 8;                     // 65536 B
    const int scan_smem  = (8192 + 512 + 1024) * 8;            // 77824 B
    cudaFuncSetAttribute(xproj_kernel,
                         cudaFuncAttributeMaxDynamicSharedMemorySize, xproj_smem);
    cudaFuncSetAttribute(rnn_scan_kernel,
                         cudaFuncAttributeMaxDynamicSharedMemorySize, scan_smem);

    xproj_kernel<<<(RNN_B * RNN_T) / 64, 256, xproj_smem>>>(x, W, bias, out);
    rnn_scan_kernel<<<RNN_B / 2, 256, scan_smem>>>(W, h0, out);
}